// round 8
// baseline (speedup 1.0000x reference)
#include <cuda_runtime.h>
#include <math.h>

#define N_NODES 50000
#define N_PAD   50016   // padded to 32-row multiple for the GEMM tiler
#define HID     64
#define R_REL   4
#define E_EDGES 200000
#define SCAN_BLK 49     // 49 blocks x 1024 elems >= 50000, per relation

// ---- persistent scratch (device globals; no allocations) ----
__device__ float g_x [(size_t)N_PAD * HID];            // current node features
__device__ float g_xl[(size_t)R_REL * N_PAD * HID];    // [r][node][64]
__device__ float g_xr[(size_t)R_REL * N_PAD * HID];    // [r][node][64]
__device__ __align__(16) int g_deg [R_REL * N_NODES];  // in-degree per (r,node)
__device__ __align__(16) int g_pos [R_REL * N_NODES];  // excl prefix -> end after scatter
__device__ int g_srcs[(size_t)R_REL * E_EDGES];        // srcs grouped by dst
__device__ int g_bsum[R_REL * SCAN_BLK];               // scan partials

__device__ __forceinline__ float gelu_exact(float v) {
    return 0.5f * v * (1.0f + erff(v * 0.70710678118654752440f));
}
__device__ __forceinline__ unsigned long long pack2(float lo, float hi) {
    unsigned long long r;
    asm("mov.b64 %0, {%1,%2};" : "=l"(r) : "f"(lo), "f"(hi));
    return r;
}
#define FMA2(d, a, b) asm("fma.rn.f32x2 %0, %1, %2, %0;" : "+l"(d) : "l"(a), "l"(b))

// ============================================================================
// Entry: x = gelu(LayerNorm(emb @ W + b)) ; one warp per node, 2 cols/lane
// ============================================================================
__global__ void __launch_bounds__(256) entry_kernel(
    const float* __restrict__ emb, const float* __restrict__ W,
    const float* __restrict__ b, const float* __restrict__ lng,
    const float* __restrict__ lnb)
{
    int warp = (blockIdx.x * blockDim.x + threadIdx.x) >> 5;
    int lane = threadIdx.x & 31;
    if (warp >= N_NODES) return;
    float2 v = ((const float2*)(emb + (size_t)warp * 64))[lane];
    int c0 = 2 * lane, c1 = c0 + 1;
    float acc0 = b[c0], acc1 = b[c1];
    #pragma unroll 8
    for (int kk = 0; kk < 32; kk++) {
        float ex = __shfl_sync(0xffffffffu, v.x, kk);
        float ey = __shfl_sync(0xffffffffu, v.y, kk);
        float2 wa = ((const float2*)(W + (2 * kk)     * 64))[lane];
        float2 wb = ((const float2*)(W + (2 * kk + 1) * 64))[lane];
        acc0 = fmaf(ex, wa.x, fmaf(ey, wb.x, acc0));
        acc1 = fmaf(ex, wa.y, fmaf(ey, wb.y, acc1));
    }
    float s = acc0 + acc1;
    #pragma unroll
    for (int o = 16; o > 0; o >>= 1) s += __shfl_xor_sync(0xffffffffu, s, o);
    float mu = s * (1.0f / 64.0f);
    float d0 = acc0 - mu, d1 = acc1 - mu;
    float q = d0 * d0 + d1 * d1;
    #pragma unroll
    for (int o = 16; o > 0; o >>= 1) q += __shfl_xor_sync(0xffffffffu, q, o);
    float inv = rsqrtf(q * (1.0f / 64.0f) + 1e-5f);
    float y0 = gelu_exact(d0 * inv * lng[c0] + lnb[c0]);
    float y1 = gelu_exact(d1 * inv * lng[c1] + lnb[c1]);
    ((float2*)(g_x + (size_t)warp * 64))[lane] = make_float2(y0, y1);
}

// ============================================================================
// GEMM via packed fma.rn.f32x2: out[r][N,64] = g_x[N,64] @ W[r][64][64].
// ============================================================================
__global__ void __launch_bounds__(256) gemm_kernel(
    const float* __restrict__ Wl, const float* __restrict__ Wr)
{
    __shared__ float xs[64][34];
    const float* W  = blockIdx.y ? Wr : Wl;
    float*      out = blockIdx.y ? g_xr : g_xl;
    int tid  = threadIdx.x;
    int row0 = blockIdx.x * 32;
    {
        const float4* src = (const float4*)(g_x + (size_t)row0 * 64);
        #pragma unroll
        for (int t = 0; t < 2; t++) {
            int j = tid + t * 256;
            float4 v = src[j];
            int n  = j >> 4;
            int k0 = (j & 15) * 4;
            xs[k0 + 0][n] = v.x; xs[k0 + 1][n] = v.y;
            xs[k0 + 2][n] = v.z; xs[k0 + 3][n] = v.w;
        }
    }
    __syncthreads();
    int cg = tid & 63;
    int rg = tid >> 6;
    int c  = cg * 4;
    int r  = c >> 6;
    int cc = c & 63;
    const float* Wp = W + r * 4096 + cc;
    int m0 = rg * 8;
    unsigned long long acc[4][4];
    #pragma unroll
    for (int i = 0; i < 4; i++)
        acc[i][0] = acc[i][1] = acc[i][2] = acc[i][3] = 0ull;
    #pragma unroll 4
    for (int k = 0; k < 64; k++) {
        float4 w = *(const float4*)(Wp + k * 64);
        unsigned long long w0 = pack2(w.x, w.x);
        unsigned long long w1 = pack2(w.y, w.y);
        unsigned long long w2 = pack2(w.z, w.z);
        unsigned long long w3 = pack2(w.w, w.w);
        #pragma unroll
        for (int i = 0; i < 4; i++) {
            unsigned long long xp = *(const unsigned long long*)(&xs[k][m0 + 2 * i]);
            FMA2(acc[i][0], xp, w0);
            FMA2(acc[i][1], xp, w1);
            FMA2(acc[i][2], xp, w2);
            FMA2(acc[i][3], xp, w3);
        }
    }
    float* obase = out + (size_t)r * N_PAD * 64 + cc;
    #pragma unroll
    for (int i = 0; i < 4; i++) {
        float lo[4], hi[4];
        #pragma unroll
        for (int j = 0; j < 4; j++)
            asm("mov.b64 {%0,%1}, %2;" : "=f"(lo[j]), "=f"(hi[j]) : "l"(acc[i][j]));
        size_t ra = (size_t)(row0 + m0 + 2 * i);
        *(float4*)(obase + ra * 64)       = make_float4(lo[0], lo[1], lo[2], lo[3]);
        *(float4*)(obase + (ra + 1) * 64) = make_float4(hi[0], hi[1], hi[2], hi[3]);
    }
}

// ============================================================================
// CSR build: zero degrees -> histogram -> 3-step exclusive scan -> scatter
// ============================================================================
__global__ void zero_deg_kernel() {
    int i = blockIdx.x * blockDim.x + threadIdx.x;
    if (i < R_REL * N_NODES) g_deg[i] = 0;
}

__global__ void hist_kernel(const int* __restrict__ ei) {
    int i = blockIdx.x * blockDim.x + threadIdx.x;
    if (i >= R_REL * E_EDGES) return;
    int r = i / E_EDGES, e = i - r * E_EDGES;
    int d = ei[(size_t)r * 2 * E_EDGES + E_EDGES + e];
    atomicAdd(&g_deg[r * N_NODES + d], 1);
}

// block-level exclusive scan of 1024 elems (256 thr x 4), partials to g_bsum
__global__ void __launch_bounds__(256) scan1_kernel() {
    __shared__ int swarp[9];
    int b = blockIdx.x;
    int r = b / SCAN_BLK, blk = b - r * SCAN_BLK;
    int t = threadIdx.x;
    int i0 = blk * 1024 + t * 4;            // index within relation
    int gb = r * N_NODES + i0;
    int v0 = 0, v1 = 0, v2 = 0, v3 = 0;
    if (i0 + 3 < N_NODES) {
        int4 q = *(const int4*)(g_deg + gb);
        v0 = q.x; v1 = q.y; v2 = q.z; v3 = q.w;
    } else {
        if (i0 + 0 < N_NODES) v0 = g_deg[gb + 0];
        if (i0 + 1 < N_NODES) v1 = g_deg[gb + 1];
        if (i0 + 2 < N_NODES) v2 = g_deg[gb + 2];
        if (i0 + 3 < N_NODES) v3 = g_deg[gb + 3];
    }
    int s = v0 + v1 + v2 + v3;
    int x = s;
    #pragma unroll
    for (int o = 1; o < 32; o <<= 1) {
        int y = __shfl_up_sync(0xffffffffu, x, o);
        if ((t & 31) >= o) x += y;
    }
    if ((t & 31) == 31) swarp[t >> 5] = x;
    __syncthreads();
    if (t == 0) {
        int acc = 0;
        #pragma unroll
        for (int w = 0; w < 8; w++) { int tmp = swarp[w]; swarp[w] = acc; acc += tmp; }
        g_bsum[b] = acc;
    }
    __syncthreads();
    int excl = x - s + swarp[t >> 5];
    int p0 = excl, p1 = p0 + v0, p2 = p1 + v1, p3 = p2 + v2;
    if (i0 + 0 < N_NODES) g_pos[gb + 0] = p0;
    if (i0 + 1 < N_NODES) g_pos[gb + 1] = p1;
    if (i0 + 2 < N_NODES) g_pos[gb + 2] = p2;
    if (i0 + 3 < N_NODES) g_pos[gb + 3] = p3;
}

__global__ void scan2_kernel() {
    int t = threadIdx.x;
    if (t < R_REL) {
        int acc = 0;
        for (int i = 0; i < SCAN_BLK; i++) {
            int v = g_bsum[t * SCAN_BLK + i];
            g_bsum[t * SCAN_BLK + i] = acc;
            acc += v;
        }
    }
}

__global__ void __launch_bounds__(256) scan3_kernel() {
    int b = blockIdx.x;
    int r = b / SCAN_BLK, blk = b - r * SCAN_BLK;
    int add = g_bsum[b];
    int i0 = blk * 1024 + threadIdx.x * 4;
    int gb = r * N_NODES + i0;
    #pragma unroll
    for (int k = 0; k < 4; k++)
        if (i0 + k < N_NODES) g_pos[gb + k] += add;
}

__global__ void scatter_kernel(const int* __restrict__ ei) {
    int i = blockIdx.x * blockDim.x + threadIdx.x;
    if (i >= R_REL * E_EDGES) return;
    int r = i / E_EDGES, e = i - r * E_EDGES;
    int s = ei[(size_t)r * 2 * E_EDGES + e];
    int d = ei[(size_t)r * 2 * E_EDGES + E_EDGES + e];
    int p = atomicAdd(&g_pos[r * N_NODES + d], 1);
    g_srcs[(size_t)r * E_EDGES + p] = s;
}

// ============================================================================
// Fused node aggregation + combine + LN. Half-warp (16 lanes x float4) per
// node; per relation loop incoming edges (CSR) + implicit self-loop, softmax
// normalization entirely in registers, then bias/mean/gelu/LayerNorm.
// Software-pipelined xl gathers (prefetch next src row).
// ============================================================================
__global__ void __launch_bounds__(256) node_kernel(
    const float* __restrict__ att_base, const float* __restrict__ bias_base,
    const float* __restrict__ ng, const float* __restrict__ nb,
    int layer, int final_layer, float* __restrict__ dout)
{
    int warp = (blockIdx.x * blockDim.x + threadIdx.x) >> 5;
    int lane = threadIdx.x & 31;
    int hl   = lane & 15;                 // lane within half
    int n    = warp * 2 + (lane >> 4);    // node for this half (exact grid)

    float s0 = 0.f, s1 = 0.f, s2 = 0.f, s3 = 0.f;   // sum over relations

    #pragma unroll
    for (int r = 0; r < R_REL; r++) {
        const float* xl = g_xl + (size_t)r * N_PAD * 64;
        const float* xr = g_xr + (size_t)r * N_PAD * 64;
        float4 xr4  = *(const float4*)(xr + (size_t)n * 64 + hl * 4);
        float4 att4 = *(const float4*)(att_base + (layer * R_REL + r) * 64 + hl * 4);
        int cnt  = g_deg[r * N_NODES + n];
        int base = g_pos[r * N_NODES + n] - cnt;        // g_pos holds end after scatter
        const int* srcs = g_srcs + (size_t)r * E_EDGES;
        int coth = __shfl_xor_sync(0xffffffffu, cnt, 16);
        int cmax = max(cnt, coth);

        int si = (cnt > 0) ? srcs[base] : n;            // edge j; j==cnt is self-loop
        float4 xc = *(const float4*)(xl + (size_t)si * 64 + hl * 4);
        float4 acc = make_float4(0.f, 0.f, 0.f, 0.f);
        float den = 0.f;

        for (int j = 0; j <= cmax; j++) {
            int snx = (j + 1 < cnt) ? srcs[base + j + 1] : n;
            float4 xn = *(const float4*)(xl + (size_t)snx * 64 + hl * 4);

            float m0 = xc.x + xr4.x, m1 = xc.y + xr4.y;
            float m2 = xc.z + xr4.z, m3 = xc.w + xr4.w;
            m0 = fmaxf(m0, 0.2f * m0);
            m1 = fmaxf(m1, 0.2f * m1);
            m2 = fmaxf(m2, 0.2f * m2);
            m3 = fmaxf(m3, 0.2f * m3);
            float p = fmaf(m0, att4.x, fmaf(m1, att4.y, fmaf(m2, att4.z, m3 * att4.w)));
            p += __shfl_xor_sync(0xffffffffu, p, 1);
            p += __shfl_xor_sync(0xffffffffu, p, 2);    // 4 lanes of head share e_h
            float a = (j <= cnt) ? __expf(p) : 0.f;
            acc.x = fmaf(a, xc.x, acc.x);
            acc.y = fmaf(a, xc.y, acc.y);
            acc.z = fmaf(a, xc.z, acc.z);
            acc.w = fmaf(a, xc.w, acc.w);
            den += a;
            xc = xn;
        }
        float invd = 1.0f / den;
        float4 b4 = *(const float4*)(bias_base + (layer * R_REL + r) * 64 + hl * 4);
        s0 += fmaf(acc.x, invd, b4.x);
        s1 += fmaf(acc.y, invd, b4.y);
        s2 += fmaf(acc.z, invd, b4.z);
        s3 += fmaf(acc.w, invd, b4.w);
    }

    s0 = gelu_exact(s0 * 0.25f);
    s1 = gelu_exact(s1 * 0.25f);
    s2 = gelu_exact(s2 * 0.25f);
    s3 = gelu_exact(s3 * 0.25f);

    float s = s0 + s1 + s2 + s3;
    #pragma unroll
    for (int o = 8; o > 0; o >>= 1) s += __shfl_xor_sync(0xffffffffu, s, o);
    float mu = s * (1.0f / 64.0f);
    float d0 = s0 - mu, d1 = s1 - mu, d2 = s2 - mu, d3 = s3 - mu;
    float q = d0 * d0 + d1 * d1 + d2 * d2 + d3 * d3;
    #pragma unroll
    for (int o = 8; o > 0; o >>= 1) q += __shfl_xor_sync(0xffffffffu, q, o);
    float inv = rsqrtf(q * (1.0f / 64.0f) + 1e-5f);

    float4 g4 = *(const float4*)(ng + hl * 4);
    float4 n4 = *(const float4*)(nb + hl * 4);
    float y0 = fmaf(d0 * inv, g4.x, n4.x);
    float y1 = fmaf(d1 * inv, g4.y, n4.y);
    float y2 = fmaf(d2 * inv, g4.z, n4.z);
    float y3 = fmaf(d3 * inv, g4.w, n4.w);
    float* xout = final_layer ? dout : g_x;
    *(float4*)(xout + (size_t)n * 64 + hl * 4) = make_float4(y0, y1, y2, y3);
}

// ============================================================================
extern "C" void kernel_launch(void* const* d_in, const int* in_sizes, int n_in,
                              void* d_out, int out_size)
{
    const float* emb       = (const float*)d_in[0];
    const float* entry_w   = (const float*)d_in[1];
    const float* entry_b   = (const float*)d_in[2];
    const float* entry_lng = (const float*)d_in[3];
    const float* entry_lnb = (const float*)d_in[4];
    const float* conv_wl   = (const float*)d_in[5];   // [2,4,64,64]
    const float* conv_wr   = (const float*)d_in[6];
    const float* conv_att  = (const float*)d_in[7];   // [2,4,4,16]
    const float* conv_bias = (const float*)d_in[8];   // [2,4,64]
    const float* norm_g    = (const float*)d_in[9];
    const float* norm_b    = (const float*)d_in[10];
    const int*   edge_idx  = (const int*)d_in[11];    // [4,2,200000]

    // ---- CSR build (per launch; edges are launch-invariant inputs) ----
    zero_deg_kernel<<<(R_REL * N_NODES + 255) / 256, 256>>>();
    hist_kernel<<<(R_REL * E_EDGES + 255) / 256, 256>>>(edge_idx);
    scan1_kernel<<<R_REL * SCAN_BLK, 256>>>();
    scan2_kernel<<<1, 32>>>();
    scan3_kernel<<<R_REL * SCAN_BLK, 256>>>();
    scatter_kernel<<<(R_REL * E_EDGES + 255) / 256, 256>>>(edge_idx);

    entry_kernel<<<(N_NODES + 7) / 8, 256>>>(emb, entry_w, entry_b, entry_lng, entry_lnb);

    const int gemm_blocks = N_PAD / 32;               // 1563
    const int node_blocks = N_NODES / 16;             // 3125 (2 nodes/warp, 8 warps)

    for (int layer = 0; layer < 2; layer++) {
        gemm_kernel<<<dim3(gemm_blocks, 2), 256>>>(conv_wl + layer * R_REL * 4096,
                                                   conv_wr + layer * R_REL * 4096);
        node_kernel<<<node_blocks, 256>>>(conv_att, conv_bias, norm_g, norm_b,
                                          layer, layer == 1, (float*)d_out);
    }
}

// round 13
// speedup vs baseline: 1.4478x; 1.4478x over previous
#include <cuda_runtime.h>
#include <math.h>

#define N_NODES 50000
#define N_PAD   50048   // multiple of 64 for the GEMM tiler
#define HID     64
#define R_REL   4
#define E_EDGES 200000
#define SCAN_BLK 49     // 49 blocks x 1024 elems >= 50000, per relation

// ---- persistent scratch (device globals; no allocations) ----
__device__ float g_x [(size_t)N_PAD * HID];            // current node features
__device__ float g_xl[(size_t)R_REL * N_PAD * HID];    // [r][node][64]
__device__ float g_xr[(size_t)R_REL * N_PAD * HID];    // [r][node][64]
__device__ __align__(16) int g_deg [R_REL * N_NODES];  // in-degree per (r,node)
__device__ __align__(16) int g_pos [R_REL * N_NODES];  // end offset after scatter
__device__ int g_srcs[(size_t)R_REL * E_EDGES];        // srcs grouped by dst
__device__ int g_bsum[R_REL * SCAN_BLK];               // scan partials

__device__ __forceinline__ float gelu_exact(float v) {
    return 0.5f * v * (1.0f + erff(v * 0.70710678118654752440f));
}
__device__ __forceinline__ unsigned long long pack2(float lo, float hi) {
    unsigned long long r;
    asm("mov.b64 %0, {%1,%2};" : "=l"(r) : "f"(lo), "f"(hi));
    return r;
}
#define FMA2(d, a, b) asm("fma.rn.f32x2 %0, %1, %2, %0;" : "+l"(d) : "l"(a), "l"(b))

// ============================================================================
// Entry: x = gelu(LayerNorm(emb @ W + b)) ; one warp per node, 2 cols/lane
// ============================================================================
__global__ void __launch_bounds__(256) entry_kernel(
    const float* __restrict__ emb, const float* __restrict__ W,
    const float* __restrict__ b, const float* __restrict__ lng,
    const float* __restrict__ lnb)
{
    int warp = (blockIdx.x * blockDim.x + threadIdx.x) >> 5;
    int lane = threadIdx.x & 31;
    if (warp >= N_NODES) return;
    float2 v = ((const float2*)(emb + (size_t)warp * 64))[lane];
    int c0 = 2 * lane, c1 = c0 + 1;
    float acc0 = b[c0], acc1 = b[c1];
    #pragma unroll 8
    for (int kk = 0; kk < 32; kk++) {
        float ex = __shfl_sync(0xffffffffu, v.x, kk);
        float ey = __shfl_sync(0xffffffffu, v.y, kk);
        float2 wa = ((const float2*)(W + (2 * kk)     * 64))[lane];
        float2 wb = ((const float2*)(W + (2 * kk + 1) * 64))[lane];
        acc0 = fmaf(ex, wa.x, fmaf(ey, wb.x, acc0));
        acc1 = fmaf(ex, wa.y, fmaf(ey, wb.y, acc1));
    }
    float s = acc0 + acc1;
    #pragma unroll
    for (int o = 16; o > 0; o >>= 1) s += __shfl_xor_sync(0xffffffffu, s, o);
    float mu = s * (1.0f / 64.0f);
    float d0 = acc0 - mu, d1 = acc1 - mu;
    float q = d0 * d0 + d1 * d1;
    #pragma unroll
    for (int o = 16; o > 0; o >>= 1) q += __shfl_xor_sync(0xffffffffu, q, o);
    float inv = rsqrtf(q * (1.0f / 64.0f) + 1e-5f);
    float y0 = gelu_exact(d0 * inv * lng[c0] + lnb[c0]);
    float y1 = gelu_exact(d1 * inv * lng[c1] + lnb[c1]);
    ((float2*)(g_x + (size_t)warp * 64))[lane] = make_float2(y0, y1);
}

// ============================================================================
// GEMM via packed fma.rn.f32x2: out[r][N,64] = g_x[N,64] @ W[r][64][64].
// 256 thr, 64 rows/block; thread tile 16 rows (8 packed pairs) x 4 cols.
// x staged TRANSPOSED in smem (stride 68 -> LDS.128 of 2 row-pairs, broadcast).
// ============================================================================
__global__ void __launch_bounds__(256) gemm_kernel(
    const float* __restrict__ Wl, const float* __restrict__ Wr)
{
    __shared__ float xs[64][68];
    const float* W  = blockIdx.y ? Wr : Wl;
    float*      out = blockIdx.y ? g_xr : g_xl;
    int tid  = threadIdx.x;
    int row0 = blockIdx.x * 64;
    {   // stage + transpose: 64x64 floats = 1024 float4
        const float4* src = (const float4*)(g_x + (size_t)row0 * 64);
        #pragma unroll
        for (int t = 0; t < 4; t++) {
            int j = tid + t * 256;
            float4 v = src[j];
            int n  = j >> 4;           // row 0..63
            int k0 = (j & 15) * 4;     // k base
            xs[k0 + 0][n] = v.x; xs[k0 + 1][n] = v.y;
            xs[k0 + 2][n] = v.z; xs[k0 + 3][n] = v.w;
        }
    }
    __syncthreads();
    int cg = tid & 63;            // column group (4 cols)
    int rg = tid >> 6;            // row group (16 rows)
    int c  = cg * 4;              // global col 0..255
    int r  = c >> 6;              // relation
    int cc = c & 63;
    const float* Wp = W + r * 4096 + cc;
    int m0 = rg * 16;
    unsigned long long acc[8][4]; // [rowpair][col]
    #pragma unroll
    for (int i = 0; i < 8; i++)
        acc[i][0] = acc[i][1] = acc[i][2] = acc[i][3] = 0ull;
    #pragma unroll 4
    for (int k = 0; k < 64; k++) {
        float4 w = *(const float4*)(Wp + k * 64);
        unsigned long long w0 = pack2(w.x, w.x);
        unsigned long long w1 = pack2(w.y, w.y);
        unsigned long long w2 = pack2(w.z, w.z);
        unsigned long long w3 = pack2(w.w, w.w);
        #pragma unroll
        for (int i = 0; i < 4; i++) {
            ulonglong2 xp = *(const ulonglong2*)(&xs[k][m0 + 4 * i]);
            FMA2(acc[2*i  ][0], xp.x, w0);
            FMA2(acc[2*i  ][1], xp.x, w1);
            FMA2(acc[2*i  ][2], xp.x, w2);
            FMA2(acc[2*i  ][3], xp.x, w3);
            FMA2(acc[2*i+1][0], xp.y, w0);
            FMA2(acc[2*i+1][1], xp.y, w1);
            FMA2(acc[2*i+1][2], xp.y, w2);
            FMA2(acc[2*i+1][3], xp.y, w3);
        }
    }
    float* obase = out + (size_t)r * N_PAD * 64 + cc;
    #pragma unroll
    for (int i = 0; i < 8; i++) {
        float lo[4], hi[4];
        #pragma unroll
        for (int j = 0; j < 4; j++)
            asm("mov.b64 {%0,%1}, %2;" : "=f"(lo[j]), "=f"(hi[j]) : "l"(acc[i][j]));
        size_t ra = (size_t)(row0 + m0 + 2 * i);
        *(float4*)(obase + ra * 64)       = make_float4(lo[0], lo[1], lo[2], lo[3]);
        *(float4*)(obase + (ra + 1) * 64) = make_float4(hi[0], hi[1], hi[2], hi[3]);
    }
}

// ============================================================================
// CSR build: zero degrees -> histogram -> 3-step exclusive scan -> scatter
// ============================================================================
__global__ void zero_deg_kernel() {
    int i = blockIdx.x * blockDim.x + threadIdx.x;
    if (i < R_REL * N_NODES) g_deg[i] = 0;
}

__global__ void hist_kernel(const int* __restrict__ ei) {
    int i = blockIdx.x * blockDim.x + threadIdx.x;
    if (i >= R_REL * E_EDGES) return;
    int r = i / E_EDGES, e = i - r * E_EDGES;
    int d = ei[(size_t)r * 2 * E_EDGES + E_EDGES + e];
    atomicAdd(&g_deg[r * N_NODES + d], 1);
}

// block-level exclusive scan of 1024 elems (256 thr x 4), partials to g_bsum
__global__ void __launch_bounds__(256) scan1_kernel() {
    __shared__ int swarp[9];
    int b = blockIdx.x;
    int r = b / SCAN_BLK, blk = b - r * SCAN_BLK;
    int t = threadIdx.x;
    int i0 = blk * 1024 + t * 4;            // index within relation
    int gb = r * N_NODES + i0;
    int v0 = 0, v1 = 0, v2 = 0, v3 = 0;
    if (i0 + 3 < N_NODES) {
        int4 q = *(const int4*)(g_deg + gb);
        v0 = q.x; v1 = q.y; v2 = q.z; v3 = q.w;
    } else {
        if (i0 + 0 < N_NODES) v0 = g_deg[gb + 0];
        if (i0 + 1 < N_NODES) v1 = g_deg[gb + 1];
        if (i0 + 2 < N_NODES) v2 = g_deg[gb + 2];
        if (i0 + 3 < N_NODES) v3 = g_deg[gb + 3];
    }
    int s = v0 + v1 + v2 + v3;
    int x = s;
    #pragma unroll
    for (int o = 1; o < 32; o <<= 1) {
        int y = __shfl_up_sync(0xffffffffu, x, o);
        if ((t & 31) >= o) x += y;
    }
    if ((t & 31) == 31) swarp[t >> 5] = x;
    __syncthreads();
    if (t == 0) {
        int acc = 0;
        #pragma unroll
        for (int w = 0; w < 8; w++) { int tmp = swarp[w]; swarp[w] = acc; acc += tmp; }
        g_bsum[b] = acc;
    }
    __syncthreads();
    int excl = x - s + swarp[t >> 5];
    int p0 = excl, p1 = p0 + v0, p2 = p1 + v1, p3 = p2 + v2;
    if (i0 + 0 < N_NODES) g_pos[gb + 0] = p0;
    if (i0 + 1 < N_NODES) g_pos[gb + 1] = p1;
    if (i0 + 2 < N_NODES) g_pos[gb + 2] = p2;
    if (i0 + 3 < N_NODES) g_pos[gb + 3] = p3;
}

// warp-per-relation exclusive scan of SCAN_BLK partials (2 elems/thread)
__global__ void scan2_kernel() {
    int w = threadIdx.x >> 5, t = threadIdx.x & 31;
    if (w >= R_REL) return;
    int* base = g_bsum + w * SCAN_BLK;
    int v0 = (t      < SCAN_BLK) ? base[t]      : 0;
    int v1 = (t + 32 < SCAN_BLK) ? base[t + 32] : 0;
    int x = v0;
    #pragma unroll
    for (int o = 1; o < 32; o <<= 1) {
        int y = __shfl_up_sync(0xffffffffu, x, o);
        if (t >= o) x += y;
    }
    int tot32 = __shfl_sync(0xffffffffu, x, 31);
    int x1 = v1;
    #pragma unroll
    for (int o = 1; o < 32; o <<= 1) {
        int y = __shfl_up_sync(0xffffffffu, x1, o);
        if (t >= o) x1 += y;
    }
    if (t      < SCAN_BLK) base[t]      = x - v0;
    if (t + 32 < SCAN_BLK) base[t + 32] = x1 - v1 + tot32;
}

__global__ void __launch_bounds__(256) scan3_kernel() {
    int b = blockIdx.x;
    int r = b / SCAN_BLK, blk = b - r * SCAN_BLK;
    int add = g_bsum[b];
    int i0 = blk * 1024 + threadIdx.x * 4;
    int gb = r * N_NODES + i0;
    #pragma unroll
    for (int k = 0; k < 4; k++)
        if (i0 + k < N_NODES) g_pos[gb + k] += add;
}

__global__ void scatter_kernel(const int* __restrict__ ei) {
    int i = blockIdx.x * blockDim.x + threadIdx.x;
    if (i >= R_REL * E_EDGES) return;
    int r = i / E_EDGES, e = i - r * E_EDGES;
    int s = ei[(size_t)r * 2 * E_EDGES + e];
    int d = ei[(size_t)r * 2 * E_EDGES + E_EDGES + e];
    int p = atomicAdd(&g_pos[r * N_NODES + d], 1);
    g_srcs[(size_t)r * E_EDGES + p] = s;
}

// ============================================================================
// Fused node aggregation + combine + LN. Half-warp (16 lanes x float4) per
// node. Edges processed in BATCHES OF 4: all 4 src indices then all 4 row
// gathers issued before any compute (MLP=4/half, 8/warp). Softmax kept in
// registers; no atomics anywhere.
// ============================================================================
__global__ void __launch_bounds__(256) node_kernel(
    const float* __restrict__ att_base, const float* __restrict__ bias_base,
    const float* __restrict__ ng, const float* __restrict__ nb,
    int layer, int final_layer, float* __restrict__ dout)
{
    int warp = (blockIdx.x * blockDim.x + threadIdx.x) >> 5;
    int lane = threadIdx.x & 31;
    int hl   = lane & 15;                 // lane within half
    int n    = warp * 2 + (lane >> 4);    // node (exact grid: 3125 blocks)
    if (n >= N_NODES) return;             // never taken (defensive)

    int cntA[R_REL], baseA[R_REL];
    #pragma unroll
    for (int r = 0; r < R_REL; r++) {
        cntA[r]  = g_deg[r * N_NODES + n];
        baseA[r] = g_pos[r * N_NODES + n] - cntA[r];   // g_pos holds end
    }

    float s0 = 0.f, s1 = 0.f, s2 = 0.f, s3 = 0.f;

    #pragma unroll
    for (int r = 0; r < R_REL; r++) {
        const float* xl = g_xl + (size_t)r * N_PAD * 64;
        const float* xr = g_xr + (size_t)r * N_PAD * 64;
        float4 xr4  = *(const float4*)(xr + (size_t)n * 64 + hl * 4);
        float4 att4 = *(const float4*)(att_base + (layer * R_REL + r) * 64 + hl * 4);
        const int* srcs = g_srcs + (size_t)r * E_EDGES + baseA[r];
        int cnt   = cntA[r];
        int total = cnt + 1;                           // + self-loop
        int toth  = __shfl_xor_sync(0xffffffffu, total, 16);
        int tmax  = max(total, toth);

        float4 acc = make_float4(0.f, 0.f, 0.f, 0.f);
        float den = 0.f;

        for (int jb = 0; jb < tmax; jb += 4) {
            int q0 = (jb + 0 < cnt) ? srcs[jb + 0] : n;
            int q1 = (jb + 1 < cnt) ? srcs[jb + 1] : n;
            int q2 = (jb + 2 < cnt) ? srcs[jb + 2] : n;
            int q3 = (jb + 3 < cnt) ? srcs[jb + 3] : n;
            float4 f0 = *(const float4*)(xl + (size_t)q0 * 64 + hl * 4);
            float4 f1 = *(const float4*)(xl + (size_t)q1 * 64 + hl * 4);
            float4 f2 = *(const float4*)(xl + (size_t)q2 * 64 + hl * 4);
            float4 f3 = *(const float4*)(xl + (size_t)q3 * 64 + hl * 4);
            #pragma unroll
            for (int k = 0; k < 4; k++) {
                float4 xc = (k == 0) ? f0 : (k == 1) ? f1 : (k == 2) ? f2 : f3;
                float m0 = xc.x + xr4.x, m1 = xc.y + xr4.y;
                float m2 = xc.z + xr4.z, m3 = xc.w + xr4.w;
                m0 = fmaxf(m0, 0.2f * m0);
                m1 = fmaxf(m1, 0.2f * m1);
                m2 = fmaxf(m2, 0.2f * m2);
                m3 = fmaxf(m3, 0.2f * m3);
                float p = fmaf(m0, att4.x, fmaf(m1, att4.y, fmaf(m2, att4.z, m3 * att4.w)));
                p += __shfl_xor_sync(0xffffffffu, p, 1);
                p += __shfl_xor_sync(0xffffffffu, p, 2);
                float a = (jb + k < total) ? __expf(p) : 0.f;
                acc.x = fmaf(a, xc.x, acc.x);
                acc.y = fmaf(a, xc.y, acc.y);
                acc.z = fmaf(a, xc.z, acc.z);
                acc.w = fmaf(a, xc.w, acc.w);
                den += a;
            }
        }
        float invd = 1.0f / den;
        float4 b4 = *(const float4*)(bias_base + (layer * R_REL + r) * 64 + hl * 4);
        s0 += fmaf(acc.x, invd, b4.x);
        s1 += fmaf(acc.y, invd, b4.y);
        s2 += fmaf(acc.z, invd, b4.z);
        s3 += fmaf(acc.w, invd, b4.w);
    }

    s0 = gelu_exact(s0 * 0.25f);
    s1 = gelu_exact(s1 * 0.25f);
    s2 = gelu_exact(s2 * 0.25f);
    s3 = gelu_exact(s3 * 0.25f);

    float s = s0 + s1 + s2 + s3;
    #pragma unroll
    for (int o = 8; o > 0; o >>= 1) s += __shfl_xor_sync(0xffffffffu, s, o);
    float mu = s * (1.0f / 64.0f);
    float d0 = s0 - mu, d1 = s1 - mu, d2 = s2 - mu, d3 = s3 - mu;
    float q = d0 * d0 + d1 * d1 + d2 * d2 + d3 * d3;
    #pragma unroll
    for (int o = 8; o > 0; o >>= 1) q += __shfl_xor_sync(0xffffffffu, q, o);
    float inv = rsqrtf(q * (1.0f / 64.0f) + 1e-5f);

    float4 g4 = *(const float4*)(ng + hl * 4);
    float4 n4 = *(const float4*)(nb + hl * 4);
    float y0 = fmaf(d0 * inv, g4.x, n4.x);
    float y1 = fmaf(d1 * inv, g4.y, n4.y);
    float y2 = fmaf(d2 * inv, g4.z, n4.z);
    float y3 = fmaf(d3 * inv, g4.w, n4.w);
    float* xout = final_layer ? dout : g_x;
    *(float4*)(xout + (size_t)n * 64 + hl * 4) = make_float4(y0, y1, y2, y3);
}

// ============================================================================
extern "C" void kernel_launch(void* const* d_in, const int* in_sizes, int n_in,
                              void* d_out, int out_size)
{
    const float* emb       = (const float*)d_in[0];
    const float* entry_w   = (const float*)d_in[1];
    const float* entry_b   = (const float*)d_in[2];
    const float* entry_lng = (const float*)d_in[3];
    const float* entry_lnb = (const float*)d_in[4];
    const float* conv_wl   = (const float*)d_in[5];   // [2,4,64,64]
    const float* conv_wr   = (const float*)d_in[6];
    const float* conv_att  = (const float*)d_in[7];   // [2,4,4,16]
    const float* conv_bias = (const float*)d_in[8];   // [2,4,64]
    const float* norm_g    = (const float*)d_in[9];
    const float* norm_b    = (const float*)d_in[10];
    const int*   edge_idx  = (const int*)d_in[11];    // [4,2,200000]

    // ---- CSR build (per launch; edges are launch-invariant inputs) ----
    zero_deg_kernel<<<(R_REL * N_NODES + 255) / 256, 256>>>();
    hist_kernel<<<(R_REL * E_EDGES + 255) / 256, 256>>>(edge_idx);
    scan1_kernel<<<R_REL * SCAN_BLK, 256>>>();
    scan2_kernel<<<1, 128>>>();
    scan3_kernel<<<R_REL * SCAN_BLK, 256>>>();
    scatter_kernel<<<(R_REL * E_EDGES + 255) / 256, 256>>>(edge_idx);

    entry_kernel<<<(N_NODES + 7) / 8, 256>>>(emb, entry_w, entry_b, entry_lng, entry_lnb);

    const int gemm_blocks = N_PAD / 64;               // 782
    const int node_blocks = N_NODES / 16;             // 3125 (2 nodes/warp, 8 warps)

    for (int layer = 0; layer < 2; layer++) {
        gemm_kernel<<<dim3(gemm_blocks, 2), 256>>>(conv_wl + layer * R_REL * 4096,
                                                   conv_wr + layer * R_REL * 4096);
        node_kernel<<<node_blocks, 256>>>(conv_att, conv_bias, norm_g, norm_b,
                                          layer, layer == 1, (float*)d_out);
    }
}

// round 14
// speedup vs baseline: 1.5871x; 1.0962x over previous
#include <cuda_runtime.h>
#include <cuda_fp16.h>
#include <math.h>

#define N_NODES 50000
#define N_PAD   50048   // multiple of 64 for the GEMM tiler
#define HID     64
#define R_REL   4
#define E_EDGES 200000
#define SCAN_BLK 49     // 49 blocks x 1024 elems >= 50000, per relation

// ---- persistent scratch (device globals; no allocations) ----
__device__ float  g_x [(size_t)N_PAD * HID];            // current node features (fp32)
__device__ __half g_xl[(size_t)R_REL * N_PAD * HID];    // [r][node][64] fp16
__device__ __half g_xr[(size_t)R_REL * N_PAD * HID];    // [r][node][64] fp16
__device__ __align__(16) int g_deg [R_REL * N_NODES];   // in-degree per (r,node)
__device__ __align__(16) int g_pos [R_REL * N_NODES];   // end offset after scatter
__device__ int g_srcs[(size_t)R_REL * E_EDGES];         // srcs grouped by dst
__device__ int g_bsum[R_REL * SCAN_BLK];                // scan partials

__device__ __forceinline__ float gelu_exact(float v) {
    return 0.5f * v * (1.0f + erff(v * 0.70710678118654752440f));
}
__device__ __forceinline__ unsigned long long pack2(float lo, float hi) {
    unsigned long long r;
    asm("mov.b64 %0, {%1,%2};" : "=l"(r) : "f"(lo), "f"(hi));
    return r;
}
#define FMA2(d, a, b) asm("fma.rn.f32x2 %0, %1, %2, %0;" : "+l"(d) : "l"(a), "l"(b))

__device__ __forceinline__ float4 ld_half4(const __half* p) {
    uint2 u = *(const uint2*)p;
    __half2 h0 = *reinterpret_cast<const __half2*>(&u.x);
    __half2 h1 = *reinterpret_cast<const __half2*>(&u.y);
    float2 f0 = __half22float2(h0);
    float2 f1 = __half22float2(h1);
    return make_float4(f0.x, f0.y, f1.x, f1.y);
}

// ============================================================================
// Entry: x = gelu(LayerNorm(emb @ W + b)) ; one warp per node, 2 cols/lane
// ============================================================================
__global__ void __launch_bounds__(256) entry_kernel(
    const float* __restrict__ emb, const float* __restrict__ W,
    const float* __restrict__ b, const float* __restrict__ lng,
    const float* __restrict__ lnb)
{
    int warp = (blockIdx.x * blockDim.x + threadIdx.x) >> 5;
    int lane = threadIdx.x & 31;
    if (warp >= N_NODES) return;
    float2 v = ((const float2*)(emb + (size_t)warp * 64))[lane];
    int c0 = 2 * lane, c1 = c0 + 1;
    float acc0 = b[c0], acc1 = b[c1];
    #pragma unroll 8
    for (int kk = 0; kk < 32; kk++) {
        float ex = __shfl_sync(0xffffffffu, v.x, kk);
        float ey = __shfl_sync(0xffffffffu, v.y, kk);
        float2 wa = ((const float2*)(W + (2 * kk)     * 64))[lane];
        float2 wb = ((const float2*)(W + (2 * kk + 1) * 64))[lane];
        acc0 = fmaf(ex, wa.x, fmaf(ey, wb.x, acc0));
        acc1 = fmaf(ex, wa.y, fmaf(ey, wb.y, acc1));
    }
    float s = acc0 + acc1;
    #pragma unroll
    for (int o = 16; o > 0; o >>= 1) s += __shfl_xor_sync(0xffffffffu, s, o);
    float mu = s * (1.0f / 64.0f);
    float d0 = acc0 - mu, d1 = acc1 - mu;
    float q = d0 * d0 + d1 * d1;
    #pragma unroll
    for (int o = 16; o > 0; o >>= 1) q += __shfl_xor_sync(0xffffffffu, q, o);
    float inv = rsqrtf(q * (1.0f / 64.0f) + 1e-5f);
    float y0 = gelu_exact(d0 * inv * lng[c0] + lnb[c0]);
    float y1 = gelu_exact(d1 * inv * lng[c1] + lnb[c1]);
    ((float2*)(g_x + (size_t)warp * 64))[lane] = make_float2(y0, y1);
}

// ============================================================================
// GEMM via packed fma.rn.f32x2: out[r][N,64] = g_x[N,64] @ W[r][64][64].
// fp32 compute, fp16 store. 256 thr, 64 rows/block; tile 16 rows x 4 cols.
// ============================================================================
__global__ void __launch_bounds__(256) gemm_kernel(
    const float* __restrict__ Wl, const float* __restrict__ Wr)
{
    __shared__ float xs[64][68];
    const float* W   = blockIdx.y ? Wr : Wl;
    __half*     out  = blockIdx.y ? g_xr : g_xl;
    int tid  = threadIdx.x;
    int row0 = blockIdx.x * 64;
    {   // stage + transpose: 64x64 floats = 1024 float4
        const float4* src = (const float4*)(g_x + (size_t)row0 * 64);
        #pragma unroll
        for (int t = 0; t < 4; t++) {
            int j = tid + t * 256;
            float4 v = src[j];
            int n  = j >> 4;
            int k0 = (j & 15) * 4;
            xs[k0 + 0][n] = v.x; xs[k0 + 1][n] = v.y;
            xs[k0 + 2][n] = v.z; xs[k0 + 3][n] = v.w;
        }
    }
    __syncthreads();
    int cg = tid & 63;
    int rg = tid >> 6;
    int c  = cg * 4;
    int r  = c >> 6;
    int cc = c & 63;
    const float* Wp = W + r * 4096 + cc;
    int m0 = rg * 16;
    unsigned long long acc[8][4];
    #pragma unroll
    for (int i = 0; i < 8; i++)
        acc[i][0] = acc[i][1] = acc[i][2] = acc[i][3] = 0ull;
    #pragma unroll 4
    for (int k = 0; k < 64; k++) {
        float4 w = *(const float4*)(Wp + k * 64);
        unsigned long long w0 = pack2(w.x, w.x);
        unsigned long long w1 = pack2(w.y, w.y);
        unsigned long long w2 = pack2(w.z, w.z);
        unsigned long long w3 = pack2(w.w, w.w);
        #pragma unroll
        for (int i = 0; i < 4; i++) {
            ulonglong2 xp = *(const ulonglong2*)(&xs[k][m0 + 4 * i]);
            FMA2(acc[2*i  ][0], xp.x, w0);
            FMA2(acc[2*i  ][1], xp.x, w1);
            FMA2(acc[2*i  ][2], xp.x, w2);
            FMA2(acc[2*i  ][3], xp.x, w3);
            FMA2(acc[2*i+1][0], xp.y, w0);
            FMA2(acc[2*i+1][1], xp.y, w1);
            FMA2(acc[2*i+1][2], xp.y, w2);
            FMA2(acc[2*i+1][3], xp.y, w3);
        }
    }
    __half* obase = out + (size_t)r * N_PAD * 64 + cc;
    #pragma unroll
    for (int i = 0; i < 8; i++) {
        float lo[4], hi[4];
        #pragma unroll
        for (int j = 0; j < 4; j++)
            asm("mov.b64 {%0,%1}, %2;" : "=f"(lo[j]), "=f"(hi[j]) : "l"(acc[i][j]));
        size_t ra = (size_t)(row0 + m0 + 2 * i);
        __half2 l01 = __floats2half2_rn(lo[0], lo[1]);
        __half2 l23 = __floats2half2_rn(lo[2], lo[3]);
        __half2 h01 = __floats2half2_rn(hi[0], hi[1]);
        __half2 h23 = __floats2half2_rn(hi[2], hi[3]);
        uint2 sl, sh;
        sl.x = *reinterpret_cast<unsigned*>(&l01); sl.y = *reinterpret_cast<unsigned*>(&l23);
        sh.x = *reinterpret_cast<unsigned*>(&h01); sh.y = *reinterpret_cast<unsigned*>(&h23);
        *(uint2*)(obase + ra * 64)       = sl;
        *(uint2*)(obase + (ra + 1) * 64) = sh;
    }
}

// ============================================================================
// CSR build: zero degrees -> histogram -> 3-step exclusive scan -> scatter
// ============================================================================
__global__ void zero_deg_kernel() {
    int i = blockIdx.x * blockDim.x + threadIdx.x;
    if (i < R_REL * N_NODES) g_deg[i] = 0;
}

__global__ void hist_kernel(const int* __restrict__ ei) {
    int i = blockIdx.x * blockDim.x + threadIdx.x;
    if (i >= R_REL * E_EDGES) return;
    int r = i / E_EDGES, e = i - r * E_EDGES;
    int d = ei[(size_t)r * 2 * E_EDGES + E_EDGES + e];
    atomicAdd(&g_deg[r * N_NODES + d], 1);
}

__global__ void __launch_bounds__(256) scan1_kernel() {
    __shared__ int swarp[9];
    int b = blockIdx.x;
    int r = b / SCAN_BLK, blk = b - r * SCAN_BLK;
    int t = threadIdx.x;
    int i0 = blk * 1024 + t * 4;
    int gb = r * N_NODES + i0;
    int v0 = 0, v1 = 0, v2 = 0, v3 = 0;
    if (i0 + 3 < N_NODES) {
        int4 q = *(const int4*)(g_deg + gb);
        v0 = q.x; v1 = q.y; v2 = q.z; v3 = q.w;
    } else {
        if (i0 + 0 < N_NODES) v0 = g_deg[gb + 0];
        if (i0 + 1 < N_NODES) v1 = g_deg[gb + 1];
        if (i0 + 2 < N_NODES) v2 = g_deg[gb + 2];
        if (i0 + 3 < N_NODES) v3 = g_deg[gb + 3];
    }
    int s = v0 + v1 + v2 + v3;
    int x = s;
    #pragma unroll
    for (int o = 1; o < 32; o <<= 1) {
        int y = __shfl_up_sync(0xffffffffu, x, o);
        if ((t & 31) >= o) x += y;
    }
    if ((t & 31) == 31) swarp[t >> 5] = x;
    __syncthreads();
    if (t == 0) {
        int acc = 0;
        #pragma unroll
        for (int w = 0; w < 8; w++) { int tmp = swarp[w]; swarp[w] = acc; acc += tmp; }
        g_bsum[b] = acc;
    }
    __syncthreads();
    int excl = x - s + swarp[t >> 5];
    int p0 = excl, p1 = p0 + v0, p2 = p1 + v1, p3 = p2 + v2;
    if (i0 + 0 < N_NODES) g_pos[gb + 0] = p0;
    if (i0 + 1 < N_NODES) g_pos[gb + 1] = p1;
    if (i0 + 2 < N_NODES) g_pos[gb + 2] = p2;
    if (i0 + 3 < N_NODES) g_pos[gb + 3] = p3;
}

__global__ void scan2_kernel() {
    int w = threadIdx.x >> 5, t = threadIdx.x & 31;
    if (w >= R_REL) return;
    int* base = g_bsum + w * SCAN_BLK;
    int v0 = (t      < SCAN_BLK) ? base[t]      : 0;
    int v1 = (t + 32 < SCAN_BLK) ? base[t + 32] : 0;
    int x = v0;
    #pragma unroll
    for (int o = 1; o < 32; o <<= 1) {
        int y = __shfl_up_sync(0xffffffffu, x, o);
        if (t >= o) x += y;
    }
    int tot32 = __shfl_sync(0xffffffffu, x, 31);
    int x1 = v1;
    #pragma unroll
    for (int o = 1; o < 32; o <<= 1) {
        int y = __shfl_up_sync(0xffffffffu, x1, o);
        if (t >= o) x1 += y;
    }
    if (t      < SCAN_BLK) base[t]      = x - v0;
    if (t + 32 < SCAN_BLK) base[t + 32] = x1 - v1 + tot32;
}

__global__ void __launch_bounds__(256) scan3_kernel() {
    int b = blockIdx.x;
    int r = b / SCAN_BLK, blk = b - r * SCAN_BLK;
    int add = g_bsum[b];
    int i0 = blk * 1024 + threadIdx.x * 4;
    int gb = r * N_NODES + i0;
    #pragma unroll
    for (int k = 0; k < 4; k++)
        if (i0 + k < N_NODES) g_pos[gb + k] += add;
}

__global__ void scatter_kernel(const int* __restrict__ ei) {
    int i = blockIdx.x * blockDim.x + threadIdx.x;
    if (i >= R_REL * E_EDGES) return;
    int r = i / E_EDGES, e = i - r * E_EDGES;
    int s = ei[(size_t)r * 2 * E_EDGES + e];
    int d = ei[(size_t)r * 2 * E_EDGES + E_EDGES + e];
    int p = atomicAdd(&g_pos[r * N_NODES + d], 1);
    g_srcs[(size_t)r * E_EDGES + p] = s;
}

// ============================================================================
// Fused node aggregation + combine + LN. Half-warp (16 lanes) per node, fp16
// row gathers (uint2/lane), batch-4 MLP. Per-half independent loop bounds via
// half-masked shuffles (all xor offsets <= 8 stay inside the 16-lane half).
// ============================================================================
__global__ void __launch_bounds__(256) node_kernel(
    const float* __restrict__ att_base, const float* __restrict__ bias_base,
    const float* __restrict__ ng, const float* __restrict__ nb,
    int layer, int final_layer, float* __restrict__ dout)
{
    int warp = (blockIdx.x * blockDim.x + threadIdx.x) >> 5;
    int lane = threadIdx.x & 31;
    int hl   = lane & 15;
    int n    = warp * 2 + (lane >> 4);
    if (n >= N_NODES) return;                         // never taken (defensive)
    const unsigned hm = 0xffffu << (lane & 16);       // this half's mask

    int cntA[R_REL], baseA[R_REL];
    #pragma unroll
    for (int r = 0; r < R_REL; r++) {
        cntA[r]  = g_deg[r * N_NODES + n];
        baseA[r] = g_pos[r * N_NODES + n] - cntA[r];
    }

    float s0 = 0.f, s1 = 0.f, s2 = 0.f, s3 = 0.f;

    #pragma unroll
    for (int r = 0; r < R_REL; r++) {
        const __half* xl = g_xl + (size_t)r * N_PAD * 64;
        const __half* xr = g_xr + (size_t)r * N_PAD * 64;
        float4 xr4  = ld_half4(xr + (size_t)n * 64 + hl * 4);
        float4 att4 = *(const float4*)(att_base + (layer * R_REL + r) * 64 + hl * 4);
        const int* srcs = g_srcs + (size_t)r * E_EDGES + baseA[r];
        int cnt   = cntA[r];
        int total = cnt + 1;                          // + self-loop

        float4 acc = make_float4(0.f, 0.f, 0.f, 0.f);
        float den = 0.f;

        for (int jb = 0; jb < total; jb += 4) {
            int q0 = (jb + 0 < cnt) ? srcs[jb + 0] : n;
            int q1 = (jb + 1 < cnt) ? srcs[jb + 1] : n;
            int q2 = (jb + 2 < cnt) ? srcs[jb + 2] : n;
            int q3 = (jb + 3 < cnt) ? srcs[jb + 3] : n;
            float4 f0 = ld_half4(xl + (size_t)q0 * 64 + hl * 4);
            float4 f1 = ld_half4(xl + (size_t)q1 * 64 + hl * 4);
            float4 f2 = ld_half4(xl + (size_t)q2 * 64 + hl * 4);
            float4 f3 = ld_half4(xl + (size_t)q3 * 64 + hl * 4);
            #pragma unroll
            for (int k = 0; k < 4; k++) {
                float4 xc = (k == 0) ? f0 : (k == 1) ? f1 : (k == 2) ? f2 : f3;
                float m0 = xc.x + xr4.x, m1 = xc.y + xr4.y;
                float m2 = xc.z + xr4.z, m3 = xc.w + xr4.w;
                m0 = fmaxf(m0, 0.2f * m0);
                m1 = fmaxf(m1, 0.2f * m1);
                m2 = fmaxf(m2, 0.2f * m2);
                m3 = fmaxf(m3, 0.2f * m3);
                float p = fmaf(m0, att4.x, fmaf(m1, att4.y, fmaf(m2, att4.z, m3 * att4.w)));
                p += __shfl_xor_sync(hm, p, 1);
                p += __shfl_xor_sync(hm, p, 2);
                float a = (jb + k < total) ? __expf(p) : 0.f;
                acc.x = fmaf(a, xc.x, acc.x);
                acc.y = fmaf(a, xc.y, acc.y);
                acc.z = fmaf(a, xc.z, acc.z);
                acc.w = fmaf(a, xc.w, acc.w);
                den += a;
            }
        }
        float invd = 1.0f / den;
        float4 b4 = *(const float4*)(bias_base + (layer * R_REL + r) * 64 + hl * 4);
        s0 += fmaf(acc.x, invd, b4.x);
        s1 += fmaf(acc.y, invd, b4.y);
        s2 += fmaf(acc.z, invd, b4.z);
        s3 += fmaf(acc.w, invd, b4.w);
    }

    s0 = gelu_exact(s0 * 0.25f);
    s1 = gelu_exact(s1 * 0.25f);
    s2 = gelu_exact(s2 * 0.25f);
    s3 = gelu_exact(s3 * 0.25f);

    float s = s0 + s1 + s2 + s3;
    #pragma unroll
    for (int o = 8; o > 0; o >>= 1) s += __shfl_xor_sync(hm, s, o);
    float mu = s * (1.0f / 64.0f);
    float d0 = s0 - mu, d1 = s1 - mu, d2 = s2 - mu, d3 = s3 - mu;
    float q = d0 * d0 + d1 * d1 + d2 * d2 + d3 * d3;
    #pragma unroll
    for (int o = 8; o > 0; o >>= 1) q += __shfl_xor_sync(hm, q, o);
    float inv = rsqrtf(q * (1.0f / 64.0f) + 1e-5f);

    float4 g4 = *(const float4*)(ng + hl * 4);
    float4 n4 = *(const float4*)(nb + hl * 4);
    float y0 = fmaf(d0 * inv, g4.x, n4.x);
    float y1 = fmaf(d1 * inv, g4.y, n4.y);
    float y2 = fmaf(d2 * inv, g4.z, n4.z);
    float y3 = fmaf(d3 * inv, g4.w, n4.w);
    float* xout = final_layer ? dout : g_x;
    *(float4*)(xout + (size_t)n * 64 + hl * 4) = make_float4(y0, y1, y2, y3);
}

// ============================================================================
extern "C" void kernel_launch(void* const* d_in, const int* in_sizes, int n_in,
                              void* d_out, int out_size)
{
    const float* emb       = (const float*)d_in[0];
    const float* entry_w   = (const float*)d_in[1];
    const float* entry_b   = (const float*)d_in[2];
    const float* entry_lng = (const float*)d_in[3];
    const float* entry_lnb = (const float*)d_in[4];
    const float* conv_wl   = (const float*)d_in[5];   // [2,4,64,64]
    const float* conv_wr   = (const float*)d_in[6];
    const float* conv_att  = (const float*)d_in[7];   // [2,4,4,16]
    const float* conv_bias = (const float*)d_in[8];   // [2,4,64]
    const float* norm_g    = (const float*)d_in[9];
    const float* norm_b    = (const float*)d_in[10];
    const int*   edge_idx  = (const int*)d_in[11];    // [4,2,200000]

    const int gemm_blocks = N_PAD / 64;               // 782
    const int node_blocks = N_NODES / 16;             // 3125

    // Launch order arranged so gemm L0 is the 4th launch (ncu capture window).
    zero_deg_kernel<<<(R_REL * N_NODES + 255) / 256, 256>>>();
    entry_kernel<<<(N_NODES + 7) / 8, 256>>>(emb, entry_w, entry_b, entry_lng, entry_lnb);
    hist_kernel<<<(R_REL * E_EDGES + 255) / 256, 256>>>(edge_idx);
    gemm_kernel<<<dim3(gemm_blocks, 2), 256>>>(conv_wl, conv_wr);          // layer 0
    scan1_kernel<<<R_REL * SCAN_BLK, 256>>>();
    scan2_kernel<<<1, 128>>>();
    scan3_kernel<<<R_REL * SCAN_BLK, 256>>>();
    scatter_kernel<<<(R_REL * E_EDGES + 255) / 256, 256>>>(edge_idx);

    node_kernel<<<node_blocks, 256>>>(conv_att, conv_bias, norm_g, norm_b,
                                      0, 0, (float*)d_out);
    gemm_kernel<<<dim3(gemm_blocks, 2), 256>>>(conv_wl + R_REL * 4096,
                                               conv_wr + R_REL * 4096);    // layer 1
    node_kernel<<<node_blocks, 256>>>(conv_att, conv_bias, norm_g, norm_b,
                                      1, 1, (float*)d_out);
}

// round 16
// speedup vs baseline: 2.2149x; 1.3956x over previous
#include <cuda_runtime.h>
#include <cuda_fp16.h>
#include <math.h>

#define N_NODES 50000
#define N_PAD   50048   // multiple of 128 for the HMMA GEMM tiler (128*391)
#define HID     64
#define R_REL   4
#define E_EDGES 200000
#define SCAN_BLK 49     // 49 blocks x 1024 elems >= 50000, per relation
#define GEMM_RB (N_PAD / 128)   // 391 row blocks

// ---- persistent scratch (device globals; no allocations) ----
__device__ __half g_x [(size_t)N_PAD * HID];            // current node features (fp16)
__device__ __half g_xl[(size_t)R_REL * N_PAD * HID];    // [r][node][64] fp16
__device__ __half g_xr[(size_t)R_REL * N_PAD * HID];    // [r][node][64] fp16
__device__ __half g_wh[2 * 2 * R_REL * 64 * 64];        // [layer][lr][r][n][k] fp16
__device__ __align__(16) int g_deg [R_REL * N_NODES];   // in-degree per (r,node)
__device__ __align__(16) int g_pos [R_REL * N_NODES];   // end offset after scatter
__device__ int g_srcs[(size_t)R_REL * E_EDGES];         // srcs grouped by dst
__device__ int g_bsum[R_REL * SCAN_BLK];                // scan partials

__device__ __forceinline__ float gelu_exact(float v) {
    return 0.5f * v * (1.0f + erff(v * 0.70710678118654752440f));
}
__device__ __forceinline__ float4 ld_half4(const __half* p) {
    uint2 u = *(const uint2*)p;
    __half2 h0 = *reinterpret_cast<const __half2*>(&u.x);
    __half2 h1 = *reinterpret_cast<const __half2*>(&u.y);
    float2 f0 = __half22float2(h0);
    float2 f1 = __half22float2(h1);
    return make_float4(f0.x, f0.y, f1.x, f1.y);
}
__device__ __forceinline__ unsigned h2_bits(float a, float b) {
    __half2 h = __floats2half2_rn(a, b);
    return *reinterpret_cast<unsigned*>(&h);
}

#define MMA16816(c0,c1,c2,c3,a0,a1,a2,a3,b0,b1) \
  asm volatile("mma.sync.aligned.m16n8k16.row.col.f32.f16.f16.f32 " \
    "{%0,%1,%2,%3},{%4,%5,%6,%7},{%8,%9},{%0,%1,%2,%3};" \
    : "+f"(c0),"+f"(c1),"+f"(c2),"+f"(c3) \
    : "r"(a0),"r"(a1),"r"(a2),"r"(a3),"r"(b0),"r"(b1))

// ============================================================================
// Entry: x = gelu(LayerNorm(emb @ W + b)) ; one warp per node -> fp16 x
// ============================================================================
__global__ void __launch_bounds__(256) entry_kernel(
    const float* __restrict__ emb, const float* __restrict__ W,
    const float* __restrict__ b, const float* __restrict__ lng,
    const float* __restrict__ lnb)
{
    int warp = (blockIdx.x * blockDim.x + threadIdx.x) >> 5;
    int lane = threadIdx.x & 31;
    if (warp >= N_NODES) return;
    float2 v = ((const float2*)(emb + (size_t)warp * 64))[lane];
    int c0 = 2 * lane, c1 = c0 + 1;
    float acc0 = b[c0], acc1 = b[c1];
    #pragma unroll 8
    for (int kk = 0; kk < 32; kk++) {
        float ex = __shfl_sync(0xffffffffu, v.x, kk);
        float ey = __shfl_sync(0xffffffffu, v.y, kk);
        float2 wa = ((const float2*)(W + (2 * kk)     * 64))[lane];
        float2 wb = ((const float2*)(W + (2 * kk + 1) * 64))[lane];
        acc0 = fmaf(ex, wa.x, fmaf(ey, wb.x, acc0));
        acc1 = fmaf(ex, wa.y, fmaf(ey, wb.y, acc1));
    }
    float s = acc0 + acc1;
    #pragma unroll
    for (int o = 16; o > 0; o >>= 1) s += __shfl_xor_sync(0xffffffffu, s, o);
    float mu = s * (1.0f / 64.0f);
    float d0 = acc0 - mu, d1 = acc1 - mu;
    float q = d0 * d0 + d1 * d1;
    #pragma unroll
    for (int o = 16; o > 0; o >>= 1) q += __shfl_xor_sync(0xffffffffu, q, o);
    float inv = rsqrtf(q * (1.0f / 64.0f) + 1e-5f);
    float y0 = gelu_exact(d0 * inv * lng[c0] + lnb[c0]);
    float y1 = gelu_exact(d1 * inv * lng[c1] + lnb[c1]);
    ((unsigned*)(g_x + (size_t)warp * 64))[lane] = h2_bits(y0, y1);
}

// ============================================================================
// Weight convert: g_wh[layer][lr][r][n][k] = W[layer][r][k][n] (fp32->fp16)
// ============================================================================
__global__ void wconv_kernel(const float* __restrict__ wl, const float* __restrict__ wr)
{
    int i = blockIdx.x * blockDim.x + threadIdx.x;
    if (i >= 2 * 2 * R_REL * 64 * 64) return;
    int k  = i & 63;
    int n  = (i >> 6) & 63;
    int r  = (i >> 12) & 3;
    int lr = (i >> 14) & 1;
    int l  = i >> 15;
    const float* w = lr ? wr : wl;
    g_wh[i] = __float2half(w[l * (R_REL * 4096) + r * 4096 + k * 64 + n]);
}

// ============================================================================
// HMMA GEMM: out[r][N,64] = g_x[N,64] @ W[r][64][64], fp16 in, fp32 acc,
// fp16 out. Block: 128 rows x 64 cols, 8 warps (4m x 2n), warp tile 32x32 =
// 2x4 m16n8k16. smem stride 72 halves -> conflict-free LDS.32 fragments.
// grid = (391, 8): y -> lr = y&1, relation = y>>1.
// ============================================================================
__global__ void __launch_bounds__(256) gemm_kernel(int layer)
{
    __shared__ __half xs[128 * 72];
    __shared__ __half ws[64 * 72];
    int tid = threadIdx.x;
    int lr  = blockIdx.y & 1;
    int r   = blockIdx.y >> 1;
    int row0 = blockIdx.x * 128;

    {   // stage x: 128x64 halves = 1024 uint4
        const uint4* src = (const uint4*)(g_x + (size_t)row0 * 64);
        #pragma unroll
        for (int t = 0; t < 4; t++) {
            int j = tid + t * 256;
            int row = j >> 3, ch = j & 7;
            *(uint4*)(xs + row * 72 + ch * 8) = src[j];
        }
    }
    {   // stage W slice [n][k]: 64x64 halves = 512 uint4
        const uint4* src = (const uint4*)(g_wh + (((layer * 2 + lr) * R_REL + r) << 12));
        #pragma unroll
        for (int t = 0; t < 2; t++) {
            int j = tid + t * 256;
            int row = j >> 3, ch = j & 7;
            *(uint4*)(ws + row * 72 + ch * 8) = src[j];
        }
    }
    __syncthreads();

    int w    = tid >> 5, lane = tid & 31;
    int g    = lane >> 2, t4 = lane & 3;
    int wm   = (w & 3) * 32;           // warp row base
    int wn   = (w >> 2) * 32;          // warp col base

    float c[2][4][4];
    #pragma unroll
    for (int mi = 0; mi < 2; mi++)
        #pragma unroll
        for (int ni = 0; ni < 4; ni++)
            c[mi][ni][0] = c[mi][ni][1] = c[mi][ni][2] = c[mi][ni][3] = 0.f;

    #pragma unroll
    for (int kc = 0; kc < 4; kc++) {
        int k0 = kc * 16;
        unsigned a[2][4], b[4][2];
        #pragma unroll
        for (int mi = 0; mi < 2; mi++) {
            const __half* base = xs + (wm + mi * 16) * 72 + k0 + t4 * 2;
            a[mi][0] = *(const unsigned*)(base + g * 72);
            a[mi][1] = *(const unsigned*)(base + (g + 8) * 72);
            a[mi][2] = *(const unsigned*)(base + g * 72 + 8);
            a[mi][3] = *(const unsigned*)(base + (g + 8) * 72 + 8);
        }
        #pragma unroll
        for (int ni = 0; ni < 4; ni++) {
            const __half* base = ws + (wn + ni * 8 + g) * 72 + k0 + t4 * 2;
            b[ni][0] = *(const unsigned*)(base);
            b[ni][1] = *(const unsigned*)(base + 8);
        }
        #pragma unroll
        for (int mi = 0; mi < 2; mi++)
            #pragma unroll
            for (int ni = 0; ni < 4; ni++)
                MMA16816(c[mi][ni][0], c[mi][ni][1], c[mi][ni][2], c[mi][ni][3],
                         a[mi][0], a[mi][1], a[mi][2], a[mi][3],
                         b[ni][0], b[ni][1]);
    }

    __half* out = (lr ? g_xr : g_xl) + (size_t)r * N_PAD * 64;
    #pragma unroll
    for (int mi = 0; mi < 2; mi++) {
        #pragma unroll
        for (int ni = 0; ni < 4; ni++) {
            size_t row = (size_t)(row0 + wm + mi * 16 + g);
            int col = wn + ni * 8 + t4 * 2;
            *(unsigned*)(out + row * 64 + col)       = h2_bits(c[mi][ni][0], c[mi][ni][1]);
            *(unsigned*)(out + (row + 8) * 64 + col) = h2_bits(c[mi][ni][2], c[mi][ni][3]);
        }
    }
}

// ============================================================================
// CSR build: zero degrees -> histogram -> 3-step exclusive scan -> scatter
// ============================================================================
__global__ void zero_deg_kernel() {
    int i = blockIdx.x * blockDim.x + threadIdx.x;
    if (i < R_REL * N_NODES) g_deg[i] = 0;
}

__global__ void hist_kernel(const int* __restrict__ ei) {
    int i = blockIdx.x * blockDim.x + threadIdx.x;
    if (i >= R_REL * E_EDGES) return;
    int r = i / E_EDGES, e = i - r * E_EDGES;
    int d = ei[(size_t)r * 2 * E_EDGES + E_EDGES + e];
    atomicAdd(&g_deg[r * N_NODES + d], 1);
}

__global__ void __launch_bounds__(256) scan1_kernel() {
    __shared__ int swarp[9];
    int b = blockIdx.x;
    int r = b / SCAN_BLK, blk = b - r * SCAN_BLK;
    int t = threadIdx.x;
    int i0 = blk * 1024 + t * 4;
    int gb = r * N_NODES + i0;
    int v0 = 0, v1 = 0, v2 = 0, v3 = 0;
    if (i0 + 3 < N_NODES) {
        int4 q = *(const int4*)(g_deg + gb);
        v0 = q.x; v1 = q.y; v2 = q.z; v3 = q.w;
    } else {
        if (i0 + 0 < N_NODES) v0 = g_deg[gb + 0];
        if (i0 + 1 < N_NODES) v1 = g_deg[gb + 1];
        if (i0 + 2 < N_NODES) v2 = g_deg[gb + 2];
        if (i0 + 3 < N_NODES) v3 = g_deg[gb + 3];
    }
    int s = v0 + v1 + v2 + v3;
    int x = s;
    #pragma unroll
    for (int o = 1; o < 32; o <<= 1) {
        int y = __shfl_up_sync(0xffffffffu, x, o);
        if ((t & 31) >= o) x += y;
    }
    if ((t & 31) == 31) swarp[t >> 5] = x;
    __syncthreads();
    if (t == 0) {
        int acc = 0;
        #pragma unroll
        for (int w = 0; w < 8; w++) { int tmp = swarp[w]; swarp[w] = acc; acc += tmp; }
        g_bsum[b] = acc;
    }
    __syncthreads();
    int excl = x - s + swarp[t >> 5];
    int p0 = excl, p1 = p0 + v0, p2 = p1 + v1, p3 = p2 + v2;
    if (i0 + 0 < N_NODES) g_pos[gb + 0] = p0;
    if (i0 + 1 < N_NODES) g_pos[gb + 1] = p1;
    if (i0 + 2 < N_NODES) g_pos[gb + 2] = p2;
    if (i0 + 3 < N_NODES) g_pos[gb + 3] = p3;
}

__global__ void scan2_kernel() {
    int w = threadIdx.x >> 5, t = threadIdx.x & 31;
    if (w >= R_REL) return;
    int* base = g_bsum + w * SCAN_BLK;
    int v0 = (t      < SCAN_BLK) ? base[t]      : 0;
    int v1 = (t + 32 < SCAN_BLK) ? base[t + 32] : 0;
    int x = v0;
    #pragma unroll
    for (int o = 1; o < 32; o <<= 1) {
        int y = __shfl_up_sync(0xffffffffu, x, o);
        if (t >= o) x += y;
    }
    int tot32 = __shfl_sync(0xffffffffu, x, 31);
    int x1 = v1;
    #pragma unroll
    for (int o = 1; o < 32; o <<= 1) {
        int y = __shfl_up_sync(0xffffffffu, x1, o);
        if (t >= o) x1 += y;
    }
    if (t      < SCAN_BLK) base[t]      = x - v0;
    if (t + 32 < SCAN_BLK) base[t + 32] = x1 - v1 + tot32;
}

__global__ void __launch_bounds__(256) scan3_kernel() {
    int b = blockIdx.x;
    int r = b / SCAN_BLK, blk = b - r * SCAN_BLK;
    int add = g_bsum[b];
    int i0 = blk * 1024 + threadIdx.x * 4;
    int gb = r * N_NODES + i0;
    #pragma unroll
    for (int k = 0; k < 4; k++)
        if (i0 + k < N_NODES) g_pos[gb + k] += add;
}

__global__ void scatter_kernel(const int* __restrict__ ei) {
    int i = blockIdx.x * blockDim.x + threadIdx.x;
    if (i >= R_REL * E_EDGES) return;
    int r = i / E_EDGES, e = i - r * E_EDGES;
    int s = ei[(size_t)r * 2 * E_EDGES + e];
    int d = ei[(size_t)r * 2 * E_EDGES + E_EDGES + e];
    int p = atomicAdd(&g_pos[r * N_NODES + d], 1);
    g_srcs[(size_t)r * E_EDGES + p] = s;
}

// ============================================================================
// Fused node aggregation + combine + LN. Half-warp (16 lanes) per node, fp16
// row gathers, batch-4 MLP, per-half loop bounds via half-masked shuffles.
// Writes fp16 g_x (layer 0) or fp32 d_out (final layer).
// ============================================================================
__global__ void __launch_bounds__(256) node_kernel(
    const float* __restrict__ att_base, const float* __restrict__ bias_base,
    const float* __restrict__ ng, const float* __restrict__ nb,
    int layer, int final_layer, float* __restrict__ dout)
{
    int warp = (blockIdx.x * blockDim.x + threadIdx.x) >> 5;
    int lane = threadIdx.x & 31;
    int hl   = lane & 15;
    int n    = warp * 2 + (lane >> 4);
    if (n >= N_NODES) return;                         // never taken (defensive)
    const unsigned hm = 0xffffu << (lane & 16);       // this half's mask

    int cntA[R_REL], baseA[R_REL];
    #pragma unroll
    for (int r = 0; r < R_REL; r++) {
        cntA[r]  = g_deg[r * N_NODES + n];
        baseA[r] = g_pos[r * N_NODES + n] - cntA[r];
    }

    float s0 = 0.f, s1 = 0.f, s2 = 0.f, s3 = 0.f;

    #pragma unroll
    for (int r = 0; r < R_REL; r++) {
        const __half* xl = g_xl + (size_t)r * N_PAD * 64;
        const __half* xr = g_xr + (size_t)r * N_PAD * 64;
        float4 xr4  = ld_half4(xr + (size_t)n * 64 + hl * 4);
        float4 att4 = *(const float4*)(att_base + (layer * R_REL + r) * 64 + hl * 4);
        const int* srcs = g_srcs + (size_t)r * E_EDGES + baseA[r];
        int cnt   = cntA[r];
        int total = cnt + 1;                          // + self-loop

        float4 acc = make_float4(0.f, 0.f, 0.f, 0.f);
        float den = 0.f;

        for (int jb = 0; jb < total; jb += 4) {
            int q0 = (jb + 0 < cnt) ? srcs[jb + 0] : n;
            int q1 = (jb + 1 < cnt) ? srcs[jb + 1] : n;
            int q2 = (jb + 2 < cnt) ? srcs[jb + 2] : n;
            int q3 = (jb + 3 < cnt) ? srcs[jb + 3] : n;
            float4 f0 = ld_half4(xl + (size_t)q0 * 64 + hl * 4);
            float4 f1 = ld_half4(xl + (size_t)q1 * 64 + hl * 4);
            float4 f2 = ld_half4(xl + (size_t)q2 * 64 + hl * 4);
            float4 f3 = ld_half4(xl + (size_t)q3 * 64 + hl * 4);
            #pragma unroll
            for (int k = 0; k < 4; k++) {
                float4 xc = (k == 0) ? f0 : (k == 1) ? f1 : (k == 2) ? f2 : f3;
                float m0 = xc.x + xr4.x, m1 = xc.y + xr4.y;
                float m2 = xc.z + xr4.z, m3 = xc.w + xr4.w;
                m0 = fmaxf(m0, 0.2f * m0);
                m1 = fmaxf(m1, 0.2f * m1);
                m2 = fmaxf(m2, 0.2f * m2);
                m3 = fmaxf(m3, 0.2f * m3);
                float p = fmaf(m0, att4.x, fmaf(m1, att4.y, fmaf(m2, att4.z, m3 * att4.w)));
                p += __shfl_xor_sync(hm, p, 1);
                p += __shfl_xor_sync(hm, p, 2);
                float a = (jb + k < total) ? __expf(p) : 0.f;
                acc.x = fmaf(a, xc.x, acc.x);
                acc.y = fmaf(a, xc.y, acc.y);
                acc.z = fmaf(a, xc.z, acc.z);
                acc.w = fmaf(a, xc.w, acc.w);
                den += a;
            }
        }
        float invd = 1.0f / den;
        float4 b4 = *(const float4*)(bias_base + (layer * R_REL + r) * 64 + hl * 4);
        s0 += fmaf(acc.x, invd, b4.x);
        s1 += fmaf(acc.y, invd, b4.y);
        s2 += fmaf(acc.z, invd, b4.z);
        s3 += fmaf(acc.w, invd, b4.w);
    }

    s0 = gelu_exact(s0 * 0.25f);
    s1 = gelu_exact(s1 * 0.25f);
    s2 = gelu_exact(s2 * 0.25f);
    s3 = gelu_exact(s3 * 0.25f);

    float s = s0 + s1 + s2 + s3;
    #pragma unroll
    for (int o = 8; o > 0; o >>= 1) s += __shfl_xor_sync(hm, s, o);
    float mu = s * (1.0f / 64.0f);
    float d0 = s0 - mu, d1 = s1 - mu, d2 = s2 - mu, d3 = s3 - mu;
    float q = d0 * d0 + d1 * d1 + d2 * d2 + d3 * d3;
    #pragma unroll
    for (int o = 8; o > 0; o >>= 1) q += __shfl_xor_sync(hm, q, o);
    float inv = rsqrtf(q * (1.0f / 64.0f) + 1e-5f);

    float4 g4 = *(const float4*)(ng + hl * 4);
    float4 n4 = *(const float4*)(nb + hl * 4);
    float y0 = fmaf(d0 * inv, g4.x, n4.x);
    float y1 = fmaf(d1 * inv, g4.y, n4.y);
    float y2 = fmaf(d2 * inv, g4.z, n4.z);
    float y3 = fmaf(d3 * inv, g4.w, n4.w);
    if (final_layer) {
        *(float4*)(dout + (size_t)n * 64 + hl * 4) = make_float4(y0, y1, y2, y3);
    } else {
        uint2 p;
        p.x = h2_bits(y0, y1);
        p.y = h2_bits(y2, y3);
        *(uint2*)(g_x + (size_t)n * 64 + hl * 4) = p;
    }
}

// ============================================================================
extern "C" void kernel_launch(void* const* d_in, const int* in_sizes, int n_in,
                              void* d_out, int out_size)
{
    const float* emb       = (const float*)d_in[0];
    const float* entry_w   = (const float*)d_in[1];
    const float* entry_b   = (const float*)d_in[2];
    const float* entry_lng = (const float*)d_in[3];
    const float* entry_lnb = (const float*)d_in[4];
    const float* conv_wl   = (const float*)d_in[5];   // [2,4,64,64]
    const float* conv_wr   = (const float*)d_in[6];
    const float* conv_att  = (const float*)d_in[7];   // [2,4,4,16]
    const float* conv_bias = (const float*)d_in[8];   // [2,4,64]
    const float* norm_g    = (const float*)d_in[9];
    const float* norm_b    = (const float*)d_in[10];
    const int*   edge_idx  = (const int*)d_in[11];    // [4,2,200000]

    const int node_blocks = N_NODES / 16;             // 3125

    // Order arranged so gemm L0 is the 4th launch (ncu capture window).
    zero_deg_kernel<<<(R_REL * N_NODES + 255) / 256, 256>>>();
    entry_kernel<<<(N_NODES + 7) / 8, 256>>>(emb, entry_w, entry_b, entry_lng, entry_lnb);
    wconv_kernel<<<(2 * 2 * R_REL * 4096 + 255) / 256, 256>>>(conv_wl, conv_wr);
    gemm_kernel<<<dim3(GEMM_RB, 8), 256>>>(0);                      // layer 0
    hist_kernel<<<(R_REL * E_EDGES + 255) / 256, 256>>>(edge_idx);
    scan1_kernel<<<R_REL * SCAN_BLK, 256>>>();
    scan2_kernel<<<1, 128>>>();
    scan3_kernel<<<R_REL * SCAN_BLK, 256>>>();
    scatter_kernel<<<(R_REL * E_EDGES + 255) / 256, 256>>>(edge_idx);

    node_kernel<<<node_blocks, 256>>>(conv_att, conv_bias, norm_g, norm_b,
                                      0, 0, (float*)d_out);
    gemm_kernel<<<dim3(GEMM_RB, 8), 256>>>(1);                      // layer 1
    node_kernel<<<node_blocks, 256>>>(conv_att, conv_bias, norm_g, norm_b,
                                      1, 1, (float*)d_out);
}